// round 10
// baseline (speedup 1.0000x reference)
#include <cuda_runtime.h>
#include <cuda_bf16.h>
#include <cstdint>

// Constants: B=16, C=128, T=8, BR=16, S=8, SY=64, INPUT_SIZE=16384, C*T*BR=16384
// seg_on = (count>=16 of 64), branch_on = (count>=4 of 8)
// Output = layer2 branch_on at t==0 -> (16,128,16) float32

__device__ __align__(16) uint16_t g_xbits[16384];
__device__ __align__(16) uint16_t g_act1[16384];

__device__ __forceinline__ uint32_t maj3(uint32_t a, uint32_t b, uint32_t c) {
    return (a & b) | (a & c) | (b & c);
}

#define SHFLX(v, m) __shfl_xor_sync(0xffffffffu, (v), (m))

// Warp processes ONE branch (512 synapses): lane L owns 16 synapses
// (seg = L>>2, quarter q = L&3), provided as 4 int4s. Table slot for synapse
// index i is sx[i+8] (slot 7 holds 0 for i == -1).
// Returns on ALL lanes the 16-bit batch mask of branch_on (>=4 of 8 segments
// with count>=16 of 64).
__device__ __forceinline__ uint32_t branch_mask(int4 d0, int4 d1, int4 d2, int4 d3,
                                                const uint16_t* __restrict__ sx) {
    uint32_t m0 = sx[d0.x + 8], m1 = sx[d0.y + 8], m2 = sx[d0.z + 8], m3 = sx[d0.w + 8];
    uint32_t m4 = sx[d1.x + 8], m5 = sx[d1.y + 8], m6 = sx[d1.z + 8], m7 = sx[d1.w + 8];
    uint32_t m8 = sx[d2.x + 8], m9 = sx[d2.y + 8], mA = sx[d2.z + 8], mB = sx[d2.w + 8];
    uint32_t mC = sx[d3.x + 8], mD = sx[d3.y + 8], mE = sx[d3.z + 8], mF = sx[d3.w + 8];

    // Wallace-8 #1: sum(m0..m7) = a1 + 2*a2 + 4*a4 + 8*a8
    uint32_t s1 = m0 ^ m1 ^ m2, c1 = maj3(m0, m1, m2);
    uint32_t s2 = m3 ^ m4 ^ m5, c2 = maj3(m3, m4, m5);
    uint32_t s3 = s1 ^ s2 ^ m6, c3 = maj3(s1, s2, m6);
    uint32_t a1 = s3 ^ m7,      c4 = s3 & m7;
    uint32_t s4 = c1 ^ c2 ^ c3, c5 = maj3(c1, c2, c3);
    uint32_t a2 = s4 ^ c4,      c6 = s4 & c4;
    uint32_t a4 = c5 ^ c6,      a8 = c5 & c6;
    // Wallace-8 #2: sum(m8..mF)
    uint32_t u1 = m8 ^ m9 ^ mA, e1 = maj3(m8, m9, mA);
    uint32_t u2 = mB ^ mC ^ mD, e2 = maj3(mB, mC, mD);
    uint32_t u3 = u1 ^ u2 ^ mE, e3 = maj3(u1, u2, mE);
    uint32_t b1 = u3 ^ mF,      e4 = u3 & mF;
    uint32_t u4 = e1 ^ e2 ^ e3, e5 = maj3(e1, e2, e3);
    uint32_t b2 = u4 ^ e4,      e6 = u4 & e4;
    uint32_t b4 = e5 ^ e6,      b8 = e5 & e6;

    // ripple: (<=8) + (<=8) -> <=16 in slices v0..v4
    uint32_t k  = a1 & b1;
    uint32_t v0 = a1 ^ b1;
    uint32_t v1 = a2 ^ b2 ^ k;  k = maj3(a2, b2, k);
    uint32_t v2 = a4 ^ b4 ^ k;  k = maj3(a4, b4, k);
    uint32_t v3 = a8 ^ b8 ^ k;
    uint32_t v4 = a8 & b8 | (a8 ^ b8) & k;   // maj3

    // merge level 1 (xor 1): <=16 + <=16 -> <=32 in t0..t5
    uint32_t r0 = SHFLX(v0, 1), r1 = SHFLX(v1, 1), r2 = SHFLX(v2, 1),
             r3 = SHFLX(v3, 1), r4 = SHFLX(v4, 1);
    k = v0 & r0;
    uint32_t t0 = v0 ^ r0;
    uint32_t t1 = v1 ^ r1 ^ k;  k = maj3(v1, r1, k);
    uint32_t t2 = v2 ^ r2 ^ k;  k = maj3(v2, r2, k);
    uint32_t t3 = v3 ^ r3 ^ k;  k = maj3(v3, r3, k);
    uint32_t t4 = v4 ^ r4 ^ k;
    uint32_t t5 = maj3(v4, r4, k);

    // merge level 2 (xor 2): need only (sum >= 16) = any bit>=4 of (<=32 + <=32)
    r0 = SHFLX(t0, 2); r1 = SHFLX(t1, 2); r2 = SHFLX(t2, 2); r3 = SHFLX(t3, 2);
    r4 = SHFLX(t4, 2); uint32_t r5 = SHFLX(t5, 2);
    k = t0 & r0;
    k = maj3(t1, r1, k);
    k = maj3(t2, r2, k);
    k = maj3(t3, r3, k);                 // carry into bit 4
    uint32_t segmask = t4 | r4 | t5 | r5 | k;   // seg_on for this lane's segment

    // branch reduction: >=4 of 8 segments (seg = lane>>2; xor4 -> seg^1, etc.)
    uint32_t p  = SHFLX(segmask, 4);
    uint32_t c0 = segmask ^ p, cc1 = segmask & p;          // count <= 2
    uint32_t q0 = SHFLX(c0, 8), q1 = SHFLX(cc1, 8);
    k = c0 & q0;
    uint32_t f0 = c0 ^ q0;
    uint32_t f1 = cc1 ^ q1 ^ k;
    uint32_t f2 = maj3(cc1, q1, k);                        // count <= 4
    uint32_t h0 = SHFLX(f0, 16), h1 = SHFLX(f1, 16), h2 = SHFLX(f2, 16);
    k = f0 & h0;
    uint32_t k2 = maj3(f1, h1, k);
    return f2 | h2 | k2;                                   // >= 4 of 8
}

// Vectorized table fill: table entry j -> sx[j+8]; slots 0..7 zeroed (-1 -> 7).
__device__ __forceinline__ void fill_table(uint16_t* sx, const uint16_t* gtab) {
    const uint4* src = reinterpret_cast<const uint4*>(gtab);   // 2048 uint4
    uint4* dst = reinterpret_cast<uint4*>(sx + 8);
    for (int i = threadIdx.x; i < 2048; i += 256) dst[i] = src[i];
    if (threadIdx.x < 8) sx[threadIdx.x] = 0;
    __syncthreads();
}

// Pack x (16 x 16384 floats of {0,1}) into per-position 16-bit batch masks.
__global__ void __launch_bounds__(256) k_pack(const float* __restrict__ x) {
    int j = blockIdx.x * 256 + threadIdx.x;
    float v[16];
#pragma unroll
    for (int b = 0; b < 16; b++) v[b] = x[b * 16384 + j];
    uint32_t m = 0;
#pragma unroll
    for (int b = 0; b < 16; b++)
        m |= (v[b] != 0.0f) ? (1u << b) : 0u;
    g_xbits[j] = (uint16_t)m;
}

// Layer 1: 512 blocks x 8 warps; warp = 4 branches, one per iteration,
// depth-2 register lookahead on the 4 int4 loads per branch.
__global__ void __launch_bounds__(256, 4) k_layer1(const int* __restrict__ idx) {
    __shared__ __align__(16) uint16_t sx[16400];
    fill_table(sx, g_xbits);

    int w = threadIdx.x >> 5, lane = threadIdx.x & 31;
    int seg = lane >> 2, q = lane & 3;
    int b0 = (blockIdx.x * 8 + w) * 4;
    const int4* base = reinterpret_cast<const int4*>(idx + b0 * 512 + seg * 64 + q * 16);
    // branch stride = 512 ints = 128 int4s

    int4 buf[2][4];
#pragma unroll
    for (int i = 0; i < 4; i++) buf[0][i] = base[i];
#pragma unroll
    for (int i = 0; i < 4; i++) buf[1][i] = base[128 + i];

#pragma unroll
    for (int it = 0; it < 4; it++) {
        int4 d0 = buf[it & 1][0], d1 = buf[it & 1][1];
        int4 d2 = buf[it & 1][2], d3 = buf[it & 1][3];
        if (it < 2) {
#pragma unroll
            for (int i = 0; i < 4; i++) buf[it & 1][i] = base[(it + 2) * 128 + i];
        }
        uint32_t ge4 = branch_mask(d0, d1, d2, d3, sx);
        if (lane == 0) g_act1[b0 + it] = (uint16_t)ge4;
    }
}

// Layer 2 (t==0 only): 256 blocks x 8 warps; warp = one (c,br) branch.
__global__ void __launch_bounds__(256, 4) k_layer2(const int* __restrict__ idx,
                                                   float* __restrict__ out) {
    __shared__ __align__(16) uint16_t sx[16400];
    fill_table(sx, g_act1);

    int w = threadIdx.x >> 5, lane = threadIdx.x & 31;
    int seg = lane >> 2, q = lane & 3;
    int pr = blockIdx.x * 8 + w;                 // branch id = c*16 + br
    int c = pr >> 4, br = pr & 15;
    // idx2 flat offset of (c, t=0, br, seg, q*16)
    const int4* base = reinterpret_cast<const int4*>(
        idx + (c * 1024 + br * 8 + seg) * 64 + q * 16);

    int4 d0 = base[0], d1 = base[1], d2 = base[2], d3 = base[3];
    uint32_t ge4 = branch_mask(d0, d1, d2, d3, sx);

    if (lane < 16)
        out[(lane * 128 + c) * 16 + br] = ((ge4 >> lane) & 1u) ? 1.0f : 0.0f;
}

extern "C" void kernel_launch(void* const* d_in, const int* in_sizes, int n_in,
                              void* d_out, int out_size) {
    const float* x = nullptr;
    const int* idxA = nullptr;
    const int* idxB = nullptr;
    for (int i = 0; i < n_in; i++) {
        if (in_sizes[i] == 262144 && !x) {
            x = (const float*)d_in[i];
        } else if (!idxA) {
            idxA = (const int*)d_in[i];
        } else if (!idxB) {
            idxB = (const int*)d_in[i];
        }
    }
    if (!x) { x = (const float*)d_in[0]; idxA = (const int*)d_in[1]; idxB = (const int*)d_in[2]; }

    float* out = (float*)d_out;   // (16, 128, 16) float32

    k_pack  <<<64, 256>>>(x);
    k_layer1<<<512, 256>>>(idxA);
    k_layer2<<<256, 256>>>(idxB, out);
}

// round 11
// speedup vs baseline: 1.1082x; 1.1082x over previous
#include <cuda_runtime.h>
#include <cuda_bf16.h>
#include <cstdint>

// Constants: B=16, C=128, T=8, BR=16, S=8, SY=64, INPUT_SIZE=16384, C*T*BR=16384
// seg_on = (count>=16 of 64), branch_on = (count>=4 of 8)
// Output = layer2 branch_on at t==0 -> (16,128,16) float32

__device__ __align__(16) uint16_t g_xbits[16384];
__device__ __align__(16) uint16_t g_act1[16384];

__device__ __forceinline__ uint32_t maj3(uint32_t a, uint32_t b, uint32_t c) {
    return (a & b) | (a & c) | (b & c);
}

#define SHFLX(v, m) __shfl_xor_sync(0xffffffffu, (v), (m))

// Warp processes ONE branch (512 synapses): lane L owns 16 synapses
// (seg = L>>2, quarter q = L&3) given as 4 int4s. Table: sx[i+8], slot 7 = 0
// for i == -1. Returns on ALL lanes the 16-bit batch mask of branch_on.
__device__ __forceinline__ uint32_t branch_mask(int4 d0, int4 d1, int4 d2, int4 d3,
                                                const uint16_t* __restrict__ sx) {
    uint32_t m0 = sx[d0.x + 8], m1 = sx[d0.y + 8], m2 = sx[d0.z + 8], m3 = sx[d0.w + 8];
    uint32_t m4 = sx[d1.x + 8], m5 = sx[d1.y + 8], m6 = sx[d1.z + 8], m7 = sx[d1.w + 8];
    uint32_t m8 = sx[d2.x + 8], m9 = sx[d2.y + 8], mA = sx[d2.z + 8], mB = sx[d2.w + 8];
    uint32_t mC = sx[d3.x + 8], mD = sx[d3.y + 8], mE = sx[d3.z + 8], mF = sx[d3.w + 8];

    // Wallace-8 #1: sum(m0..m7) = a1 + 2*a2 + 4*a4 + 8*a8
    uint32_t s1 = m0 ^ m1 ^ m2, c1 = maj3(m0, m1, m2);
    uint32_t s2 = m3 ^ m4 ^ m5, c2 = maj3(m3, m4, m5);
    uint32_t s3 = s1 ^ s2 ^ m6, c3 = maj3(s1, s2, m6);
    uint32_t a1 = s3 ^ m7,      c4 = s3 & m7;
    uint32_t s4 = c1 ^ c2 ^ c3, c5 = maj3(c1, c2, c3);
    uint32_t a2 = s4 ^ c4,      c6 = s4 & c4;
    uint32_t a4 = c5 ^ c6,      a8 = c5 & c6;
    // Wallace-8 #2: sum(m8..mF)
    uint32_t u1 = m8 ^ m9 ^ mA, e1 = maj3(m8, m9, mA);
    uint32_t u2 = mB ^ mC ^ mD, e2 = maj3(mB, mC, mD);
    uint32_t u3 = u1 ^ u2 ^ mE, e3 = maj3(u1, u2, mE);
    uint32_t b1 = u3 ^ mF,      e4 = u3 & mF;
    uint32_t u4 = e1 ^ e2 ^ e3, e5 = maj3(e1, e2, e3);
    uint32_t b2 = u4 ^ e4,      e6 = u4 & e4;
    uint32_t b4 = e5 ^ e6,      b8 = e5 & e6;

    // ripple: (<=8) + (<=8) -> <=16 in slices v0..v4
    uint32_t k  = a1 & b1;
    uint32_t v0 = a1 ^ b1;
    uint32_t v1 = a2 ^ b2 ^ k;  k = maj3(a2, b2, k);
    uint32_t v2 = a4 ^ b4 ^ k;  k = maj3(a4, b4, k);
    uint32_t v3 = a8 ^ b8 ^ k;
    uint32_t v4 = maj3(a8, b8, k);

    // merge level 1 (xor 1): <=16 + <=16 -> <=32
    uint32_t r0 = SHFLX(v0, 1), r1 = SHFLX(v1, 1), r2 = SHFLX(v2, 1),
             r3 = SHFLX(v3, 1), r4 = SHFLX(v4, 1);
    k = v0 & r0;
    uint32_t t0 = v0 ^ r0;
    uint32_t t1 = v1 ^ r1 ^ k;  k = maj3(v1, r1, k);
    uint32_t t2 = v2 ^ r2 ^ k;  k = maj3(v2, r2, k);
    uint32_t t3 = v3 ^ r3 ^ k;  k = maj3(v3, r3, k);
    uint32_t t4 = v4 ^ r4 ^ k;
    uint32_t t5 = maj3(v4, r4, k);

    // merge level 2 (xor 2): need only (sum >= 16)
    r0 = SHFLX(t0, 2); r1 = SHFLX(t1, 2); r2 = SHFLX(t2, 2); r3 = SHFLX(t3, 2);
    r4 = SHFLX(t4, 2); uint32_t r5 = SHFLX(t5, 2);
    k = t0 & r0;
    k = maj3(t1, r1, k);
    k = maj3(t2, r2, k);
    k = maj3(t3, r3, k);
    uint32_t segmask = t4 | r4 | t5 | r5 | k;   // seg_on for lane's segment

    // branch reduction: >=4 of 8 segments via xor 4/8/16
    uint32_t p  = SHFLX(segmask, 4);
    uint32_t c0 = segmask ^ p, cc1 = segmask & p;
    uint32_t q0 = SHFLX(c0, 8), q1 = SHFLX(cc1, 8);
    k = c0 & q0;
    uint32_t f0 = c0 ^ q0;
    uint32_t f1 = cc1 ^ q1 ^ k;
    uint32_t f2 = maj3(cc1, q1, k);
    uint32_t h0 = SHFLX(f0, 16), h1 = SHFLX(f1, 16), h2 = SHFLX(f2, 16);
    k = f0 & h0;
    uint32_t k2 = maj3(f1, h1, k);
    return f2 | h2 | k2;
}

// Vectorized table fill: entry j -> sx[j+8]; slots 0..7 zeroed (-1 -> slot 7).
__device__ __forceinline__ void fill_table(uint16_t* sx, const uint16_t* gtab) {
    const uint4* src = reinterpret_cast<const uint4*>(gtab);   // 2048 uint4
    uint4* dst = reinterpret_cast<uint4*>(sx + 8);
    for (int i = threadIdx.x; i < 2048; i += 256) dst[i] = src[i];
    if (threadIdx.x < 8) sx[threadIdx.x] = 0;
    __syncthreads();
}

// Pack x (16 x 16384 floats of {0,1}) into per-position 16-bit batch masks.
__global__ void __launch_bounds__(256) k_pack(const float* __restrict__ x) {
    int j = blockIdx.x * 256 + threadIdx.x;
    float v[16];
#pragma unroll
    for (int b = 0; b < 16; b++) v[b] = x[b * 16384 + j];
    uint32_t m = 0;
#pragma unroll
    for (int b = 0; b < 16; b++)
        m |= (v[b] != 0.0f) ? (1u << b) : 0u;
    g_xbits[j] = (uint16_t)m;
    cudaTriggerProgrammaticLaunchCompletion();
}

// Layer 1: 512 blocks x 8 warps; warp = 4 branches. All 16 int4 idx loads are
// issued BEFORE cudaGridDependencySynchronize() — they do not depend on k_pack,
// so the whole 32MB stream overlaps k_pack's tail + launch gap (PDL).
__global__ void __launch_bounds__(256, 2) k_layer1(const int* __restrict__ idx) {
    __shared__ __align__(16) uint16_t sx[16400];

    int w = threadIdx.x >> 5, lane = threadIdx.x & 31;
    int seg = lane >> 2, q = lane & 3;
    int b0 = (blockIdx.x * 8 + w) * 4;
    const int4* base = reinterpret_cast<const int4*>(idx + b0 * 512 + seg * 64 + q * 16);

    int4 D0[4], D1[4], D2[4], D3[4];     // 4 branches x 4 int4 (64 regs)
#pragma unroll
    for (int i = 0; i < 4; i++) D0[i] = base[i];
#pragma unroll
    for (int i = 0; i < 4; i++) D1[i] = base[128 + i];
#pragma unroll
    for (int i = 0; i < 4; i++) D2[i] = base[256 + i];
#pragma unroll
    for (int i = 0; i < 4; i++) D3[i] = base[384 + i];

    cudaGridDependencySynchronize();      // wait for k_pack's g_xbits
    fill_table(sx, g_xbits);

    uint32_t ge0 = branch_mask(D0[0], D0[1], D0[2], D0[3], sx);
    uint32_t ge1 = branch_mask(D1[0], D1[1], D1[2], D1[3], sx);
    uint32_t ge2 = branch_mask(D2[0], D2[1], D2[2], D2[3], sx);
    uint32_t ge3 = branch_mask(D3[0], D3[1], D3[2], D3[3], sx);
    if (lane == 0) {
        g_act1[b0]     = (uint16_t)ge0;
        g_act1[b0 + 1] = (uint16_t)ge1;
        g_act1[b0 + 2] = (uint16_t)ge2;
        g_act1[b0 + 3] = (uint16_t)ge3;
    }
    cudaTriggerProgrammaticLaunchCompletion();
}

// Layer 2 (t==0 only): 256 blocks x 8 warps; warp = one (c,br) branch.
// idx2 loads issued before the dependency sync -> hidden behind k_layer1.
__global__ void __launch_bounds__(256, 4) k_layer2(const int* __restrict__ idx,
                                                   float* __restrict__ out) {
    __shared__ __align__(16) uint16_t sx[16400];

    int w = threadIdx.x >> 5, lane = threadIdx.x & 31;
    int seg = lane >> 2, q = lane & 3;
    int pr = blockIdx.x * 8 + w;                 // branch id = c*16 + br
    int c = pr >> 4, br = pr & 15;
    const int4* base = reinterpret_cast<const int4*>(
        idx + (c * 1024 + br * 8 + seg) * 64 + q * 16);

    int4 d0 = base[0], d1 = base[1], d2 = base[2], d3 = base[3];

    cudaGridDependencySynchronize();      // wait for k_layer1's g_act1
    fill_table(sx, g_act1);

    uint32_t ge4 = branch_mask(d0, d1, d2, d3, sx);
    if (lane < 16)
        out[(lane * 128 + c) * 16 + br] = ((ge4 >> lane) & 1u) ? 1.0f : 0.0f;
}

extern "C" void kernel_launch(void* const* d_in, const int* in_sizes, int n_in,
                              void* d_out, int out_size) {
    const float* x = nullptr;
    const int* idxA = nullptr;
    const int* idxB = nullptr;
    for (int i = 0; i < n_in; i++) {
        if (in_sizes[i] == 262144 && !x) {
            x = (const float*)d_in[i];
        } else if (!idxA) {
            idxA = (const int*)d_in[i];
        } else if (!idxB) {
            idxB = (const int*)d_in[i];
        }
    }
    if (!x) { x = (const float*)d_in[0]; idxA = (const int*)d_in[1]; idxB = (const int*)d_in[2]; }

    float* out = (float*)d_out;   // (16, 128, 16) float32

    // k_pack: normal launch (nothing upstream)
    k_pack<<<64, 256>>>(const_cast<float*>(x));

    // k_layer1 / k_layer2: programmatic dependent launch (overlap with upstream)
    cudaLaunchAttribute attr[1];
    attr[0].id = cudaLaunchAttributeProgrammaticStreamSerialization;
    attr[0].val.programmaticStreamSerializationAllowed = 1;

    {
        cudaLaunchConfig_t cfg = {};
        cfg.gridDim = dim3(512, 1, 1);
        cfg.blockDim = dim3(256, 1, 1);
        cfg.dynamicSmemBytes = 0;
        cfg.stream = 0;
        cfg.attrs = attr;
        cfg.numAttrs = 1;
        cudaLaunchKernelEx(&cfg, k_layer1, idxA);
    }
    {
        cudaLaunchConfig_t cfg = {};
        cfg.gridDim = dim3(256, 1, 1);
        cfg.blockDim = dim3(256, 1, 1);
        cfg.dynamicSmemBytes = 0;
        cfg.stream = 0;
        cfg.attrs = attr;
        cfg.numAttrs = 1;
        cudaLaunchKernelEx(&cfg, k_layer2, idxB, (float*)d_out);
    }
}

// round 12
// speedup vs baseline: 1.1099x; 1.0015x over previous
#include <cuda_runtime.h>
#include <cuda_bf16.h>
#include <cstdint>

// Constants: B=16, C=128, T=8, BR=16, S=8, SY=64, INPUT_SIZE=16384, C*T*BR=16384
// seg_on = (count>=16 of 64), branch_on = (count>=4 of 8)
// Output = layer2 branch_on at t==0 -> (16,128,16) float32

__device__ __align__(16) uint16_t g_xbits[16384];
__device__ __align__(16) uint16_t g_act1[16384];

__device__ __forceinline__ uint32_t maj3(uint32_t a, uint32_t b, uint32_t c) {
    return (a & b) | (a & c) | (b & c);
}

#define SHFLX(v, m) __shfl_xor_sync(0xffffffffu, (v), (m))

// Warp processes ONE branch (512 synapses): lane L owns 16 synapses
// (seg = L>>2, quarter q = L&3) given as 4 int4s. Table: sx[i+8], slot 7 = 0
// for i == -1. Returns on ALL lanes the 16-bit batch mask of branch_on.
__device__ __forceinline__ uint32_t branch_mask(int4 d0, int4 d1, int4 d2, int4 d3,
                                                const uint16_t* __restrict__ sx) {
    uint32_t m0 = sx[d0.x + 8], m1 = sx[d0.y + 8], m2 = sx[d0.z + 8], m3 = sx[d0.w + 8];
    uint32_t m4 = sx[d1.x + 8], m5 = sx[d1.y + 8], m6 = sx[d1.z + 8], m7 = sx[d1.w + 8];
    uint32_t m8 = sx[d2.x + 8], m9 = sx[d2.y + 8], mA = sx[d2.z + 8], mB = sx[d2.w + 8];
    uint32_t mC = sx[d3.x + 8], mD = sx[d3.y + 8], mE = sx[d3.z + 8], mF = sx[d3.w + 8];

    // Wallace-8 #1: sum(m0..m7) = a1 + 2*a2 + 4*a4 + 8*a8
    uint32_t s1 = m0 ^ m1 ^ m2, c1 = maj3(m0, m1, m2);
    uint32_t s2 = m3 ^ m4 ^ m5, c2 = maj3(m3, m4, m5);
    uint32_t s3 = s1 ^ s2 ^ m6, c3 = maj3(s1, s2, m6);
    uint32_t a1 = s3 ^ m7,      c4 = s3 & m7;
    uint32_t s4 = c1 ^ c2 ^ c3, c5 = maj3(c1, c2, c3);
    uint32_t a2 = s4 ^ c4,      c6 = s4 & c4;
    uint32_t a4 = c5 ^ c6,      a8 = c5 & c6;
    // Wallace-8 #2: sum(m8..mF)
    uint32_t u1 = m8 ^ m9 ^ mA, e1 = maj3(m8, m9, mA);
    uint32_t u2 = mB ^ mC ^ mD, e2 = maj3(mB, mC, mD);
    uint32_t u3 = u1 ^ u2 ^ mE, e3 = maj3(u1, u2, mE);
    uint32_t b1 = u3 ^ mF,      e4 = u3 & mF;
    uint32_t u4 = e1 ^ e2 ^ e3, e5 = maj3(e1, e2, e3);
    uint32_t b2 = u4 ^ e4,      e6 = u4 & e4;
    uint32_t b4 = e5 ^ e6,      b8 = e5 & e6;

    // ripple: (<=8) + (<=8) -> <=16 in slices v0..v4
    uint32_t k  = a1 & b1;
    uint32_t v0 = a1 ^ b1;
    uint32_t v1 = a2 ^ b2 ^ k;  k = maj3(a2, b2, k);
    uint32_t v2 = a4 ^ b4 ^ k;  k = maj3(a4, b4, k);
    uint32_t v3 = a8 ^ b8 ^ k;
    uint32_t v4 = maj3(a8, b8, k);

    // merge level 1 (xor 1): <=16 + <=16 -> <=32
    uint32_t r0 = SHFLX(v0, 1), r1 = SHFLX(v1, 1), r2 = SHFLX(v2, 1),
             r3 = SHFLX(v3, 1), r4 = SHFLX(v4, 1);
    k = v0 & r0;
    uint32_t t0 = v0 ^ r0;
    uint32_t t1 = v1 ^ r1 ^ k;  k = maj3(v1, r1, k);
    uint32_t t2 = v2 ^ r2 ^ k;  k = maj3(v2, r2, k);
    uint32_t t3 = v3 ^ r3 ^ k;  k = maj3(v3, r3, k);
    uint32_t t4 = v4 ^ r4 ^ k;
    uint32_t t5 = maj3(v4, r4, k);

    // merge level 2 (xor 2): need only (sum >= 16)
    r0 = SHFLX(t0, 2); r1 = SHFLX(t1, 2); r2 = SHFLX(t2, 2); r3 = SHFLX(t3, 2);
    r4 = SHFLX(t4, 2); uint32_t r5 = SHFLX(t5, 2);
    k = t0 & r0;
    k = maj3(t1, r1, k);
    k = maj3(t2, r2, k);
    k = maj3(t3, r3, k);
    uint32_t segmask = t4 | r4 | t5 | r5 | k;   // seg_on for lane's segment

    // branch reduction: >=4 of 8 segments via xor 4/8/16
    uint32_t p  = SHFLX(segmask, 4);
    uint32_t c0 = segmask ^ p, cc1 = segmask & p;
    uint32_t q0 = SHFLX(c0, 8), q1 = SHFLX(cc1, 8);
    k = c0 & q0;
    uint32_t f0 = c0 ^ q0;
    uint32_t f1 = cc1 ^ q1 ^ k;
    uint32_t f2 = maj3(cc1, q1, k);
    uint32_t h0 = SHFLX(f0, 16), h1 = SHFLX(f1, 16), h2 = SHFLX(f2, 16);
    k = f0 & h0;
    uint32_t k2 = maj3(f1, h1, k);
    return f2 | h2 | k2;
}

// Vectorized table fill: entry j -> sx[j+8]; slots 0..7 zeroed (-1 -> slot 7).
__device__ __forceinline__ void fill_table(uint16_t* sx, const uint16_t* gtab) {
    const uint4* src = reinterpret_cast<const uint4*>(gtab);   // 2048 uint4
    uint4* dst = reinterpret_cast<uint4*>(sx + 8);
    for (int i = threadIdx.x; i < 2048; i += 256) dst[i] = src[i];
    if (threadIdx.x < 8) sx[threadIdx.x] = 0;
    __syncthreads();
}

// Pack x (16 x 16384 floats of {0,1}) into per-position 16-bit batch masks.
__global__ void __launch_bounds__(256) k_pack(const float* __restrict__ x) {
    int j = blockIdx.x * 256 + threadIdx.x;
    float v[16];
#pragma unroll
    for (int b = 0; b < 16; b++) v[b] = x[b * 16384 + j];
    uint32_t m = 0;
#pragma unroll
    for (int b = 0; b < 16; b++)
        m |= (v[b] != 0.0f) ? (1u << b) : 0u;
    g_xbits[j] = (uint16_t)m;
    cudaTriggerProgrammaticLaunchCompletion();
}

// Layer 1: 1024 blocks x 8 warps; warp = 2 branches. The 8 int4 idx loads are
// issued BEFORE cudaGridDependencySynchronize() — independent of k_pack — so
// the 32MB stream overlaps upstream execution (PDL). Short compute chain.
__global__ void __launch_bounds__(256, 4) k_layer1(const int* __restrict__ idx) {
    __shared__ __align__(16) uint16_t sx[16400];

    int w = threadIdx.x >> 5, lane = threadIdx.x & 31;
    int seg = lane >> 2, q = lane & 3;
    int b0 = (blockIdx.x * 8 + w) * 2;
    const int4* base = reinterpret_cast<const int4*>(idx + b0 * 512 + seg * 64 + q * 16);

    int4 D0[4], D1[4];                   // 2 branches x 4 int4 (32 regs)
#pragma unroll
    for (int i = 0; i < 4; i++) D0[i] = __ldcs(base + i);
#pragma unroll
    for (int i = 0; i < 4; i++) D1[i] = __ldcs(base + 128 + i);

    cudaGridDependencySynchronize();      // wait for k_pack's g_xbits
    fill_table(sx, g_xbits);

    uint32_t ge0 = branch_mask(D0[0], D0[1], D0[2], D0[3], sx);
    uint32_t ge1 = branch_mask(D1[0], D1[1], D1[2], D1[3], sx);
    if (lane == 0) {
        g_act1[b0]     = (uint16_t)ge0;
        g_act1[b0 + 1] = (uint16_t)ge1;
    }
    cudaTriggerProgrammaticLaunchCompletion();
}

// Layer 2 (t==0 only): 256 blocks x 8 warps; warp = one (c,br) branch.
// idx2 loads issued before the dependency sync -> hidden behind k_layer1.
__global__ void __launch_bounds__(256, 4) k_layer2(const int* __restrict__ idx,
                                                   float* __restrict__ out) {
    __shared__ __align__(16) uint16_t sx[16400];

    int w = threadIdx.x >> 5, lane = threadIdx.x & 31;
    int seg = lane >> 2, q = lane & 3;
    int pr = blockIdx.x * 8 + w;                 // branch id = c*16 + br
    int c = pr >> 4, br = pr & 15;
    const int4* base = reinterpret_cast<const int4*>(
        idx + (c * 1024 + br * 8 + seg) * 64 + q * 16);

    int4 d0 = __ldcs(base);
    int4 d1 = __ldcs(base + 1);
    int4 d2 = __ldcs(base + 2);
    int4 d3 = __ldcs(base + 3);

    cudaGridDependencySynchronize();      // wait for k_layer1's g_act1
    fill_table(sx, g_act1);

    uint32_t ge4 = branch_mask(d0, d1, d2, d3, sx);
    if (lane < 16)
        out[(lane * 128 + c) * 16 + br] = ((ge4 >> lane) & 1u) ? 1.0f : 0.0f;
}

extern "C" void kernel_launch(void* const* d_in, const int* in_sizes, int n_in,
                              void* d_out, int out_size) {
    const float* x = nullptr;
    const int* idxA = nullptr;
    const int* idxB = nullptr;
    for (int i = 0; i < n_in; i++) {
        if (in_sizes[i] == 262144 && !x) {
            x = (const float*)d_in[i];
        } else if (!idxA) {
            idxA = (const int*)d_in[i];
        } else if (!idxB) {
            idxB = (const int*)d_in[i];
        }
    }
    if (!x) { x = (const float*)d_in[0]; idxA = (const int*)d_in[1]; idxB = (const int*)d_in[2]; }

    float* out = (float*)d_out;   // (16, 128, 16) float32

    // k_pack: normal launch (nothing upstream)
    k_pack<<<64, 256>>>(const_cast<float*>(x));

    // k_layer1 / k_layer2: programmatic dependent launch (overlap with upstream)
    cudaLaunchAttribute attr[1];
    attr[0].id = cudaLaunchAttributeProgrammaticStreamSerialization;
    attr[0].val.programmaticStreamSerializationAllowed = 1;

    {
        cudaLaunchConfig_t cfg = {};
        cfg.gridDim = dim3(1024, 1, 1);
        cfg.blockDim = dim3(256, 1, 1);
        cfg.dynamicSmemBytes = 0;
        cfg.stream = 0;
        cfg.attrs = attr;
        cfg.numAttrs = 1;
        cudaLaunchKernelEx(&cfg, k_layer1, idxA);
    }
    {
        cudaLaunchConfig_t cfg = {};
        cfg.gridDim = dim3(256, 1, 1);
        cfg.blockDim = dim3(256, 1, 1);
        cfg.dynamicSmemBytes = 0;
        cfg.stream = 0;
        cfg.attrs = attr;
        cfg.numAttrs = 1;
        cudaLaunchKernelEx(&cfg, k_layer2, idxB, (float*)d_out);
    }
}